// round 1
// baseline (speedup 1.0000x reference)
#include <cuda_runtime.h>
#include <cuda_bf16.h>
#include <cstdint>

// Problem constants
#define BB   256
#define TT   2048
#define IND  6
#define HID  64
#define GG   192          // 3*HID
#define DPK  64
#define NROWS (BB*TT)     // 524288
#define EPS  1e-5f

typedef unsigned long long u64;

// ---------------- scratch (allocation-free: __device__ globals) -------------
__device__ float g_x[(size_t)NROWS * HID];       // 128 MB : post input-proj activations
__device__ float g_gi[(size_t)NROWS * GG];       // 402 MB : input-side gate pre-activations
__device__ float g_hseq[(size_t)NROWS * HID];    // 128 MB : GRU hidden states

// ---------------- packed f32x2 helpers --------------------------------------
__device__ __forceinline__ u64 fma2(u64 a, u64 b, u64 c) {
    u64 d;
    asm("fma.rn.f32x2 %0, %1, %2, %3;" : "=l"(d) : "l"(a), "l"(b), "l"(c));
    return d;
}
__device__ __forceinline__ u64 pack2(float a, float b) {
    u64 r;
    asm("mov.b64 %0, {%1,%2};" : "=l"(r) : "f"(a), "f"(b));
    return r;
}
__device__ __forceinline__ float psum(u64 a) {
    return __uint_as_float((unsigned)(a & 0xffffffffull)) +
           __uint_as_float((unsigned)(a >> 32));
}

__device__ __forceinline__ float sigmoidf_(float x) {
    return __fdividef(1.f, 1.f + __expf(-x));
}
__device__ __forceinline__ float tanhf_(float x) {
    float e = __expf(2.f * x);
    return 1.f - __fdividef(2.f, e + 1.f);   // safe at e->inf (->1) and e->0 (->-1)
}

// ================== K1a: input proj + LN + exact GELU ======================
// one warp per (b,t) row; each lane owns output cols lane, lane+32
__global__ void k_inproj(const float* __restrict__ ce,
                         const float* __restrict__ w1,
                         const float* __restrict__ b1,
                         const float* __restrict__ g1,
                         const float* __restrict__ bb1)
{
    const int wid  = threadIdx.x >> 5;
    const int lane = threadIdx.x & 31;
    const size_t row = (size_t)blockIdx.x * 8 + wid;   // grid = NROWS/8

    const float* c = ce + row * IND;
    float v0 = b1[lane], v1 = b1[lane + 32];
#pragma unroll
    for (int i = 0; i < IND; ++i) {
        float ci = __ldg(c + i);
        v0 = fmaf(ci, w1[i * HID + lane],      v0);
        v1 = fmaf(ci, w1[i * HID + lane + 32], v1);
    }
    float s = v0 + v1;
#pragma unroll
    for (int o = 16; o; o >>= 1) s += __shfl_xor_sync(0xffffffffu, s, o);
    const float m = s * (1.f / 64.f);
    const float d0 = v0 - m, d1 = v1 - m;
    float q = d0 * d0 + d1 * d1;
#pragma unroll
    for (int o = 16; o; o >>= 1) q += __shfl_xor_sync(0xffffffffu, q, o);
    const float rs = rsqrtf(q * (1.f / 64.f) + EPS);
    const float y0 = d0 * rs * g1[lane]      + bb1[lane];
    const float y1 = d1 * rs * g1[lane + 32] + bb1[lane + 32];
    const float k = 0.70710678118654752f;
    g_x[row * HID + lane]      = 0.5f * y0 * (1.f + erff(y0 * k));
    g_x[row * HID + lane + 32] = 0.5f * y1 * (1.f + erff(y1 * k));
}

// ================== K1b: gi = x @ W_ih^T + b_ih ============================
// gate-stationary: thread g keeps W_ih[g,:] in 32 packed-u64 registers,
// 8 rows of x staged in smem per iteration.
__global__ void __launch_bounds__(192) k_gi(const float* __restrict__ Wih,
                                            const float* __restrict__ bih)
{
    const int g = threadIdx.x;
    u64 w[32];
    const u64* wrow = (const u64*)(Wih + g * HID);
#pragma unroll
    for (int k = 0; k < 32; ++k) w[k] = wrow[k];
    const float bi = bih[g];

    __shared__ __align__(16) float x_sh[8 * HID];

    for (size_t r0 = (size_t)blockIdx.x * 8; r0 < (size_t)NROWS;
         r0 += (size_t)gridDim.x * 8) {
        if (g < 128)
            ((float4*)x_sh)[g] = ((const float4*)(g_x + r0 * HID))[g];
        __syncthreads();
#pragma unroll
        for (int rr = 0; rr < 8; ++rr) {
            u64 a0 = 0, a1 = 0;
            const ulonglong2* xv = (const ulonglong2*)(x_sh + rr * HID);
#pragma unroll
            for (int kk = 0; kk < 16; ++kk) {
                ulonglong2 p = xv[kk];
                a0 = fma2(w[2 * kk],     p.x, a0);
                a1 = fma2(w[2 * kk + 1], p.y, a1);
            }
            g_gi[(r0 + rr) * GG + g] = psum(a0) + psum(a1) + bi;
        }
        __syncthreads();
    }
}

// ================== K2: sequential GRU recurrence ===========================
// one CTA per batch row, persistent over T=2048 steps.
// thread g in [0,192) owns gate g; W_hh[g,:] register-resident.
__global__ void __launch_bounds__(192) k_gru(const float* __restrict__ Whh,
                                             const float* __restrict__ bhh)
{
    const int g = threadIdx.x;
    const int b = blockIdx.x;

    __shared__ __align__(16) float h_sh[HID];
    __shared__ float r_sh[HID];
    __shared__ float z_sh[HID];

    u64 w[32];
    const u64* wrow = (const u64*)(Whh + g * HID);
#pragma unroll
    for (int k = 0; k < 32; ++k) w[k] = wrow[k];
    const float bh = bhh[g];

    if (g < HID) h_sh[g] = 0.f;

    const float* gi_row = g_gi + ((size_t)b * TT) * GG + g;
    float* hrow = g_hseq + ((size_t)b * TT) * HID;

    float gcur = __ldg(gi_row);     // gi for t=0
    __syncthreads();

    for (int t = 0; t < TT; ++t) {
        // prefetch next-step gi (latency hidden across a full step)
        float gnext = 0.f;
        if (t < TT - 1) gnext = __ldg(gi_row + (size_t)(t + 1) * GG);

        // hd = W_hh[g,:] . h + b_hh[g]
        u64 a0 = 0, a1 = 0, a2 = 0, a3 = 0;
        const ulonglong2* hv = (const ulonglong2*)h_sh;
#pragma unroll
        for (int kk = 0; kk < 8; ++kk) {
            ulonglong2 p = hv[2 * kk];
            ulonglong2 q = hv[2 * kk + 1];
            a0 = fma2(w[4 * kk + 0], p.x, a0);
            a1 = fma2(w[4 * kk + 1], p.y, a1);
            a2 = fma2(w[4 * kk + 2], q.x, a2);
            a3 = fma2(w[4 * kk + 3], q.y, a3);
        }
        const float hd = (psum(a0) + psum(a1)) + (psum(a2) + psum(a3)) + bh;

        if (g < 64) {
            r_sh[g] = sigmoidf_(gcur + hd);
        } else if (g < 128) {
            z_sh[g - 64] = sigmoidf_(gcur + hd);
        }
        __syncthreads();

        if (g >= 128) {
            const int j = g - 128;
            const float n    = tanhf_(gcur + r_sh[j] * hd);
            const float z    = z_sh[j];
            const float hold = h_sh[j];
            const float hnew = fmaf(z, hold - n, n);   // (1-z)*n + z*h
            h_sh[j] = hnew;
            hrow[(size_t)t * HID + j] = hnew;
        }
        gcur = gnext;
        __syncthreads();
    }
}

// ================== K3: out proj + LN =======================================
// one warp per row; lane owns output cols lane, lane+32; w2 columns in regs.
__global__ void __launch_bounds__(128) k_outproj(const float* __restrict__ w2,
                                                 const float* __restrict__ b2,
                                                 const float* __restrict__ g2,
                                                 const float* __restrict__ bb2,
                                                 float* __restrict__ out)
{
    const int wid  = threadIdx.x >> 5;
    const int lane = threadIdx.x & 31;
    const int j0 = lane, j1 = lane + 32;

    u64 wc0[32], wc1[32];
#pragma unroll
    for (int kk = 0; kk < 32; ++kk) {
        wc0[kk] = pack2(w2[(2 * kk) * DPK + j0], w2[(2 * kk + 1) * DPK + j0]);
        wc1[kk] = pack2(w2[(2 * kk) * DPK + j1], w2[(2 * kk + 1) * DPK + j1]);
    }
    const float bo0 = b2[j0], bo1 = b2[j1];
    const float lg0 = g2[j0], lg1 = g2[j1];
    const float lb0 = bb2[j0], lb1 = bb2[j1];

    __shared__ __align__(16) float hsw[4][HID];

    const size_t stride = (size_t)gridDim.x * 4;
    for (size_t row = (size_t)blockIdx.x * 4 + wid; row < (size_t)NROWS;
         row += stride) {
        float2 hv = ((const float2*)(g_hseq + row * HID))[lane];
        ((float2*)hsw[wid])[lane] = hv;
        __syncwarp();

        u64 a0 = 0, a1 = 0, a2 = 0, a3 = 0;
        const ulonglong2* hvv = (const ulonglong2*)hsw[wid];
#pragma unroll
        for (int kk = 0; kk < 16; ++kk) {
            ulonglong2 p = hvv[kk];
            a0 = fma2(wc0[2 * kk],     p.x, a0);
            a1 = fma2(wc0[2 * kk + 1], p.y, a1);
            a2 = fma2(wc1[2 * kk],     p.x, a2);
            a3 = fma2(wc1[2 * kk + 1], p.y, a3);
        }
        float o0 = psum(a0) + psum(a1) + bo0;
        float o1 = psum(a2) + psum(a3) + bo1;

        float s = o0 + o1;
#pragma unroll
        for (int o = 16; o; o >>= 1) s += __shfl_xor_sync(0xffffffffu, s, o);
        const float m = s * (1.f / 64.f);
        const float d0 = o0 - m, d1 = o1 - m;
        float q = d0 * d0 + d1 * d1;
#pragma unroll
        for (int o = 16; o; o >>= 1) q += __shfl_xor_sync(0xffffffffu, q, o);
        const float rs = rsqrtf(q * (1.f / 64.f) + EPS);

        out[row * DPK + j0] = d0 * rs * lg0 + lb0;
        out[row * DPK + j1] = d1 * rs * lg1 + lb1;
        __syncwarp();   // hsw slot reused next iteration
    }
}

// ================== launcher =================================================
extern "C" void kernel_launch(void* const* d_in, const int* in_sizes, int n_in,
                              void* d_out, int out_size)
{
    const float* drug = (const float*)d_in[0];
    const float* w1   = (const float*)d_in[1];
    const float* b1   = (const float*)d_in[2];
    const float* ln1g = (const float*)d_in[3];
    const float* ln1b = (const float*)d_in[4];
    const float* Wih  = (const float*)d_in[5];
    const float* bih  = (const float*)d_in[6];
    const float* Whh  = (const float*)d_in[7];
    const float* bhh  = (const float*)d_in[8];
    const float* w2   = (const float*)d_in[9];
    const float* b2   = (const float*)d_in[10];
    const float* ln2g = (const float*)d_in[11];
    const float* ln2b = (const float*)d_in[12];
    float* out = (float*)d_out;

    k_inproj<<<NROWS / 8, 256>>>(drug, w1, b1, ln1g, ln1b);
    k_gi<<<888, 192>>>(Wih, bih);
    k_gru<<<BB, 192>>>(Whh, bhh);
    k_outproj<<<1024, 128>>>(w2, b2, ln2g, ln2b, out);
}

// round 2
// speedup vs baseline: 1.0188x; 1.0188x over previous
#include <cuda_runtime.h>
#include <cuda_bf16.h>
#include <cstdint>

// Problem constants
#define BB   256
#define TT   2048
#define IND  6
#define HID  64
#define GG   192          // 3*HID
#define DPK  64
#define NROWS (BB*TT)     // 524288
#define EPS  1e-5f

typedef unsigned long long u64;

// ---------------- scratch (allocation-free: __device__ globals) -------------
__device__ float g_x[(size_t)NROWS * HID];       // 128 MB : post input-proj activations
__device__ float g_gi[(size_t)NROWS * GG];       // 402 MB : input-side gate pre-activations
__device__ float g_hseq[(size_t)NROWS * HID];    // 128 MB : GRU hidden states

// ---------------- packed f32x2 helpers --------------------------------------
__device__ __forceinline__ u64 fma2(u64 a, u64 b, u64 c) {
    u64 d;
    asm("fma.rn.f32x2 %0, %1, %2, %3;" : "=l"(d) : "l"(a), "l"(b), "l"(c));
    return d;
}
__device__ __forceinline__ u64 pack2(float a, float b) {
    u64 r;
    asm("mov.b64 %0, {%1,%2};" : "=l"(r) : "f"(a), "f"(b));
    return r;
}
__device__ __forceinline__ float psum(u64 a) {
    return __uint_as_float((unsigned)(a & 0xffffffffull)) +
           __uint_as_float((unsigned)(a >> 32));
}

__device__ __forceinline__ float sigmoidf_(float x) {
    return __fdividef(1.f, 1.f + __expf(-x));
}
__device__ __forceinline__ float tanhf_(float x) {
    float e = __expf(2.f * x);
    return 1.f - __fdividef(2.f, e + 1.f);   // safe at e->inf (->1) and e->0 (->-1)
}

// ================== K1a: input proj + LN + exact GELU ======================
// one warp per (b,t) row; each lane owns output cols lane, lane+32
__global__ void k_inproj(const float* __restrict__ ce,
                         const float* __restrict__ w1,
                         const float* __restrict__ b1,
                         const float* __restrict__ g1,
                         const float* __restrict__ bb1)
{
    const int wid  = threadIdx.x >> 5;
    const int lane = threadIdx.x & 31;
    const size_t row = (size_t)blockIdx.x * 8 + wid;   // grid = NROWS/8

    const float* c = ce + row * IND;
    float v0 = b1[lane], v1 = b1[lane + 32];
#pragma unroll
    for (int i = 0; i < IND; ++i) {
        float ci = __ldg(c + i);
        v0 = fmaf(ci, w1[i * HID + lane],      v0);
        v1 = fmaf(ci, w1[i * HID + lane + 32], v1);
    }
    float s = v0 + v1;
#pragma unroll
    for (int o = 16; o; o >>= 1) s += __shfl_xor_sync(0xffffffffu, s, o);
    const float m = s * (1.f / 64.f);
    const float d0 = v0 - m, d1 = v1 - m;
    float q = d0 * d0 + d1 * d1;
#pragma unroll
    for (int o = 16; o; o >>= 1) q += __shfl_xor_sync(0xffffffffu, q, o);
    const float rs = rsqrtf(q * (1.f / 64.f) + EPS);
    const float y0 = d0 * rs * g1[lane]      + bb1[lane];
    const float y1 = d1 * rs * g1[lane + 32] + bb1[lane + 32];
    const float k = 0.70710678118654752f;
    g_x[row * HID + lane]      = 0.5f * y0 * (1.f + erff(y0 * k));
    g_x[row * HID + lane + 32] = 0.5f * y1 * (1.f + erff(y1 * k));
}

// ================== K1b: gi = x @ W_ih^T + b_ih ============================
// gate-stationary: thread g keeps W_ih[g,:] in 32 packed-u64 registers,
// 8 rows of x staged in smem per iteration.
__global__ void __launch_bounds__(192) k_gi(const float* __restrict__ Wih,
                                            const float* __restrict__ bih)
{
    const int g = threadIdx.x;
    u64 w[32];
    const u64* wrow = (const u64*)(Wih + g * HID);
#pragma unroll
    for (int k = 0; k < 32; ++k) w[k] = wrow[k];
    const float bi = bih[g];

    __shared__ __align__(16) float x_sh[8 * HID];

    for (size_t r0 = (size_t)blockIdx.x * 8; r0 < (size_t)NROWS;
         r0 += (size_t)gridDim.x * 8) {
        if (g < 128)
            ((float4*)x_sh)[g] = ((const float4*)(g_x + r0 * HID))[g];
        __syncthreads();
#pragma unroll
        for (int rr = 0; rr < 8; ++rr) {
            u64 a0 = 0, a1 = 0;
            const ulonglong2* xv = (const ulonglong2*)(x_sh + rr * HID);
#pragma unroll
            for (int kk = 0; kk < 16; ++kk) {
                ulonglong2 p = xv[kk];
                a0 = fma2(w[2 * kk],     p.x, a0);
                a1 = fma2(w[2 * kk + 1], p.y, a1);
            }
            g_gi[(r0 + rr) * GG + g] = psum(a0) + psum(a1) + bi;
        }
        __syncthreads();
    }
}

// ================== K2: sequential GRU recurrence ===========================
// grid = 128 CTAs, block = 128 threads = 2 batch rows x 64 threads.
// Thread (rsel, j) owns output index j of batch row 2*blockIdx.x+rsel and
// computes ALL THREE gates for j (r,z,n never cross threads).
// r,n weights register-resident (64 u64); z weights in conflict-free smem.
// h double-buffered in smem -> exactly ONE __syncthreads per timestep.
// gi prefetched 3 steps ahead (~600cyc cover vs ~380-577cyc DRAM latency).
__global__ void __launch_bounds__(128, 1) k_gru(const float* __restrict__ Whh,
                                                const float* __restrict__ bhh)
{
    const int tid  = threadIdx.x;
    const int j    = tid & 63;
    const int rsel = tid >> 6;
    const size_t brow = (size_t)blockIdx.x * 2 + rsel;

    __shared__ __align__(16) u64   zw_s[32][64];    // z-gate weights, packed pairs
    __shared__ __align__(16) float hbuf[2][2][64];  // [phase][rsel][j]

    // stage z weights: zw_s[k2][j] = pack(Whh[(64+j)*64 + 2k2], ...+2k2+1)
    for (int idx = tid; idx < 32 * 64; idx += 128) {
        const int k2 = idx >> 6, jj = idx & 63;
        const float* zr = Whh + (size_t)(64 + jj) * HID + 2 * k2;
        zw_s[k2][jj] = pack2(zr[0], zr[1]);
    }

    // r and n weight rows register-resident
    u64 wr[32], wn[32];
    {
        const u64* rrow = (const u64*)(Whh + (size_t)j * HID);
        const u64* nrow = (const u64*)(Whh + (size_t)(128 + j) * HID);
#pragma unroll
        for (int k = 0; k < 32; ++k) { wr[k] = rrow[k]; wn[k] = nrow[k]; }
    }
    const float bhr = bhh[j];
    const float bhz = bhh[64 + j];
    const float bhn = bhh[128 + j];

    hbuf[0][rsel][j] = 0.f;
    float hprev = 0.f;

    const float* gi = g_gi + brow * TT * GG;
    float* hrow = g_hseq + brow * TT * HID;

    // gi software pipeline, depth 3
    float ir0 = __ldg(gi + 0 * GG + j),  iz0 = __ldg(gi + 0 * GG + 64 + j),  in0 = __ldg(gi + 0 * GG + 128 + j);
    float ir1 = __ldg(gi + 1 * GG + j),  iz1 = __ldg(gi + 1 * GG + 64 + j),  in1 = __ldg(gi + 1 * GG + 128 + j);
    float ir2 = __ldg(gi + 2 * GG + j),  iz2 = __ldg(gi + 2 * GG + 64 + j),  in2 = __ldg(gi + 2 * GG + 128 + j);
    __syncthreads();

    for (int t = 0; t < TT; ++t) {
        // prefetch t+3
        float fr = 0.f, fz = 0.f, fn = 0.f;
        if (t + 3 < TT) {
            const float* p = gi + (size_t)(t + 3) * GG;
            fr = __ldg(p + j); fz = __ldg(p + 64 + j); fn = __ldg(p + 128 + j);
        }

        const u64* hv = (const u64*)hbuf[t & 1][rsel];
        u64 ar = 0, az = 0, an = 0;
#pragma unroll
        for (int kk = 0; kk < 32; ++kk) {
            const u64 hk = hv[kk];
            ar = fma2(wr[kk],       hk, ar);
            az = fma2(zw_s[kk][j],  hk, az);
            an = fma2(wn[kk],       hk, an);
        }
        const float hr = psum(ar) + bhr;
        const float hz = psum(az) + bhz;
        const float hn = psum(an) + bhn;

        const float r = sigmoidf_(ir0 + hr);
        const float z = sigmoidf_(iz0 + hz);
        const float n = tanhf_(in0 + r * hn);
        const float hnew = fmaf(z, hprev - n, n);   // (1-z)*n + z*h

        hbuf[(t + 1) & 1][rsel][j] = hnew;
        hrow[(size_t)t * HID + j] = hnew;
        hprev = hnew;

        // rotate gi pipeline
        ir0 = ir1; iz0 = iz1; in0 = in1;
        ir1 = ir2; iz1 = iz2; in1 = in2;
        ir2 = fr;  iz2 = fz;  in2 = fn;

        __syncthreads();
    }
}

// ================== K3: out proj + LN =======================================
// 256 threads / 8 warps; w2 packed in smem [k2][64] (conflict-free LDS.64);
// each warp processes 2 rows per iteration (MLP=2), lane owns cols lane,lane+32.
__global__ void __launch_bounds__(256) k_outproj(const float* __restrict__ w2,
                                                 const float* __restrict__ b2,
                                                 const float* __restrict__ g2,
                                                 const float* __restrict__ bb2,
                                                 float* __restrict__ out)
{
    const int tid  = threadIdx.x;
    const int wid  = tid >> 5;
    const int lane = tid & 31;
    const int j0 = lane, j1 = lane + 32;

    __shared__ __align__(16) u64   w2p[32][64];     // 16 KB
    __shared__ __align__(16) float hst[8][2][64];   // 4 KB, per-warp staging

    for (int idx = tid; idx < 32 * 64; idx += 256) {
        const int k2 = idx >> 6, jj = idx & 63;
        w2p[k2][jj] = pack2(w2[(size_t)(2 * k2) * DPK + jj],
                            w2[(size_t)(2 * k2 + 1) * DPK + jj]);
    }
    __syncthreads();

    const float bo0 = b2[j0], bo1 = b2[j1];
    const float lg0 = g2[j0], lg1 = g2[j1];
    const float lb0 = bb2[j0], lb1 = bb2[j1];

    const size_t stride = (size_t)gridDim.x * 16;
    for (size_t base = (size_t)blockIdx.x * 16 + wid * 2; base < (size_t)NROWS;
         base += stride) {
        const size_t rowA = base, rowB = base + 1;
        const float2 ha = ((const float2*)(g_hseq + rowA * HID))[lane];
        const float2 hb = ((const float2*)(g_hseq + rowB * HID))[lane];
        ((float2*)hst[wid][0])[lane] = ha;
        ((float2*)hst[wid][1])[lane] = hb;
        __syncwarp();

        const u64* hA = (const u64*)hst[wid][0];
        const u64* hB = (const u64*)hst[wid][1];
        u64 a0 = 0, a1 = 0, c0 = 0, c1 = 0;
#pragma unroll
        for (int k2 = 0; k2 < 32; ++k2) {
            const u64 w0 = w2p[k2][j0];
            const u64 w1 = w2p[k2][j1];
            const u64 pA = hA[k2];
            const u64 pB = hB[k2];
            a0 = fma2(w0, pA, a0);
            a1 = fma2(w1, pA, a1);
            c0 = fma2(w0, pB, c0);
            c1 = fma2(w1, pB, c1);
        }

        // row A LN
        {
            float o0 = psum(a0) + bo0, o1 = psum(a1) + bo1;
            float s = o0 + o1;
#pragma unroll
            for (int o = 16; o; o >>= 1) s += __shfl_xor_sync(0xffffffffu, s, o);
            const float m = s * (1.f / 64.f);
            const float d0 = o0 - m, d1 = o1 - m;
            float q = d0 * d0 + d1 * d1;
#pragma unroll
            for (int o = 16; o; o >>= 1) q += __shfl_xor_sync(0xffffffffu, q, o);
            const float rs = rsqrtf(q * (1.f / 64.f) + EPS);
            out[rowA * DPK + j0] = d0 * rs * lg0 + lb0;
            out[rowA * DPK + j1] = d1 * rs * lg1 + lb1;
        }
        // row B LN
        {
            float o0 = psum(c0) + bo0, o1 = psum(c1) + bo1;
            float s = o0 + o1;
#pragma unroll
            for (int o = 16; o; o >>= 1) s += __shfl_xor_sync(0xffffffffu, s, o);
            const float m = s * (1.f / 64.f);
            const float d0 = o0 - m, d1 = o1 - m;
            float q = d0 * d0 + d1 * d1;
#pragma unroll
            for (int o = 16; o; o >>= 1) q += __shfl_xor_sync(0xffffffffu, q, o);
            const float rs = rsqrtf(q * (1.f / 64.f) + EPS);
            out[rowB * DPK + j0] = d0 * rs * lg0 + lb0;
            out[rowB * DPK + j1] = d1 * rs * lg1 + lb1;
        }
        __syncwarp();   // hst slot reused next iteration
    }
}

// ================== launcher =================================================
extern "C" void kernel_launch(void* const* d_in, const int* in_sizes, int n_in,
                              void* d_out, int out_size)
{
    const float* drug = (const float*)d_in[0];
    const float* w1   = (const float*)d_in[1];
    const float* b1   = (const float*)d_in[2];
    const float* ln1g = (const float*)d_in[3];
    const float* ln1b = (const float*)d_in[4];
    const float* Wih  = (const float*)d_in[5];
    const float* bih  = (const float*)d_in[6];
    const float* Whh  = (const float*)d_in[7];
    const float* bhh  = (const float*)d_in[8];
    const float* w2   = (const float*)d_in[9];
    const float* b2   = (const float*)d_in[10];
    const float* ln2g = (const float*)d_in[11];
    const float* ln2b = (const float*)d_in[12];
    float* out = (float*)d_out;

    k_inproj<<<NROWS / 8, 256>>>(drug, w1, b1, ln1g, ln1b);
    k_gi<<<888, 192>>>(Wih, bih);
    k_gru<<<BB / 2, 128>>>(Whh, bhh);
    k_outproj<<<2048, 256>>>(w2, b2, ln2g, ln2b, out);
}

// round 3
// speedup vs baseline: 1.1782x; 1.1564x over previous
#include <cuda_runtime.h>
#include <cuda_bf16.h>
#include <cstdint>

// Problem constants
#define BB   256
#define TT   2048
#define IND  6
#define HID  64
#define GG   192          // 3*HID
#define DPK  64
#define NROWS (BB*TT)     // 524288
#define EPS  1e-5f

typedef unsigned long long u64;

// ---------------- scratch (allocation-free: __device__ globals) -------------
__device__ float g_x[(size_t)NROWS * HID];       // 128 MB : post input-proj activations
__device__ float g_gi[(size_t)NROWS * GG];       // 402 MB : input-side gate pre-activations
__device__ float g_hseq[(size_t)NROWS * HID];    // 128 MB : GRU hidden states

// ---------------- packed f32x2 helpers --------------------------------------
__device__ __forceinline__ u64 fma2(u64 a, u64 b, u64 c) {
    u64 d;
    asm("fma.rn.f32x2 %0, %1, %2, %3;" : "=l"(d) : "l"(a), "l"(b), "l"(c));
    return d;
}
__device__ __forceinline__ u64 add2(u64 a, u64 b) {
    u64 d;
    asm("add.rn.f32x2 %0, %1, %2;" : "=l"(d) : "l"(a), "l"(b));
    return d;
}
__device__ __forceinline__ u64 pack2(float a, float b) {
    u64 r;
    asm("mov.b64 %0, {%1,%2};" : "=l"(r) : "f"(a), "f"(b));
    return r;
}
__device__ __forceinline__ float psum(u64 a) {
    return __uint_as_float((unsigned)(a & 0xffffffffull)) +
           __uint_as_float((unsigned)(a >> 32));
}

__device__ __forceinline__ float sigmoidf_(float x) {
    return __fdividef(1.f, 1.f + __expf(-x));
}
__device__ __forceinline__ float tanhf_(float x) {
    float e = __expf(2.f * x);
    return 1.f - __fdividef(2.f, e + 1.f);   // safe at e->inf (->1) and e->0 (->-1)
}

// ================== K1a: input proj + LN + exact GELU ======================
// one warp per (b,t) row; each lane owns output cols lane, lane+32
__global__ void k_inproj(const float* __restrict__ ce,
                         const float* __restrict__ w1,
                         const float* __restrict__ b1,
                         const float* __restrict__ g1,
                         const float* __restrict__ bb1)
{
    const int wid  = threadIdx.x >> 5;
    const int lane = threadIdx.x & 31;
    const size_t row = (size_t)blockIdx.x * 8 + wid;   // grid = NROWS/8

    const float* c = ce + row * IND;
    float v0 = b1[lane], v1 = b1[lane + 32];
#pragma unroll
    for (int i = 0; i < IND; ++i) {
        float ci = __ldg(c + i);
        v0 = fmaf(ci, w1[i * HID + lane],      v0);
        v1 = fmaf(ci, w1[i * HID + lane + 32], v1);
    }
    float s = v0 + v1;
#pragma unroll
    for (int o = 16; o; o >>= 1) s += __shfl_xor_sync(0xffffffffu, s, o);
    const float m = s * (1.f / 64.f);
    const float d0 = v0 - m, d1 = v1 - m;
    float q = d0 * d0 + d1 * d1;
#pragma unroll
    for (int o = 16; o; o >>= 1) q += __shfl_xor_sync(0xffffffffu, q, o);
    const float rs = rsqrtf(q * (1.f / 64.f) + EPS);
    const float y0 = d0 * rs * g1[lane]      + bb1[lane];
    const float y1 = d1 * rs * g1[lane + 32] + bb1[lane + 32];
    const float k = 0.70710678118654752f;
    g_x[row * HID + lane]      = 0.5f * y0 * (1.f + erff(y0 * k));
    g_x[row * HID + lane + 32] = 0.5f * y1 * (1.f + erff(y1 * k));
}

// ================== K1b: gi = x @ W_ih^T + b_ih ============================
// gate-stationary: thread g keeps W_ih[g,:] in 32 packed-u64 registers,
// 8 rows of x staged in smem per iteration.
__global__ void __launch_bounds__(192) k_gi(const float* __restrict__ Wih,
                                            const float* __restrict__ bih)
{
    const int g = threadIdx.x;
    u64 w[32];
    const u64* wrow = (const u64*)(Wih + g * HID);
#pragma unroll
    for (int k = 0; k < 32; ++k) w[k] = wrow[k];
    const float bi = bih[g];

    __shared__ __align__(16) float x_sh[8 * HID];

    for (size_t r0 = (size_t)blockIdx.x * 8; r0 < (size_t)NROWS;
         r0 += (size_t)gridDim.x * 8) {
        if (g < 128)
            ((float4*)x_sh)[g] = ((const float4*)(g_x + r0 * HID))[g];
        __syncthreads();
#pragma unroll
        for (int rr = 0; rr < 8; ++rr) {
            u64 a0 = 0, a1 = 0;
            const ulonglong2* xv = (const ulonglong2*)(x_sh + rr * HID);
#pragma unroll
            for (int kk = 0; kk < 16; ++kk) {
                ulonglong2 p = xv[kk];
                a0 = fma2(w[2 * kk],     p.x, a0);
                a1 = fma2(w[2 * kk + 1], p.y, a1);
            }
            g_gi[(r0 + rr) * GG + g] = psum(a0) + psum(a1) + bi;
        }
        __syncthreads();
    }
}

// ================== K2: sequential GRU recurrence ===========================
// grid = 128 CTAs, block = 128 threads = 2 batch rows x 64 threads.
// Thread (rsel, j) owns output index j and computes ALL THREE gates for j.
// ALL THREE gate weight rows register-resident (96 u64 = 192 regs); no smem
// weight traffic in the hot loop, everything else kept small to avoid spills.
// h double-buffered in smem -> exactly ONE __syncthreads per timestep.
// gi prefetched 2 steps ahead.
__global__ void __launch_bounds__(128, 1) k_gru(const float* __restrict__ Whh,
                                                const float* __restrict__ bhh)
{
    const int tid  = threadIdx.x;
    const int j    = tid & 63;
    const int rsel = tid >> 6;
    const size_t brow = (size_t)blockIdx.x * 2 + rsel;

    __shared__ __align__(16) float hbuf[2][2][64];  // [phase][rsel][j]

    // all three gate rows register-resident
    u64 wr[32], wz[32], wn[32];
    {
        const u64* rrow = (const u64*)(Whh + (size_t)j * HID);
        const u64* zrow = (const u64*)(Whh + (size_t)(64 + j) * HID);
        const u64* nrow = (const u64*)(Whh + (size_t)(128 + j) * HID);
#pragma unroll
        for (int k = 0; k < 32; ++k) {
            wr[k] = rrow[k];
            wz[k] = zrow[k];
            wn[k] = nrow[k];
        }
    }
    const float bhr = bhh[j];
    const float bhz = bhh[64 + j];
    const float bhn = bhh[128 + j];

    hbuf[0][rsel][j] = 0.f;
    float hprev = 0.f;

    const float* gi = g_gi + brow * TT * GG;
    float* hrow = g_hseq + brow * TT * HID;

    // gi software pipeline, depth 2
    float ir0 = __ldg(gi + 0 * GG + j), iz0 = __ldg(gi + 0 * GG + 64 + j), in0 = __ldg(gi + 0 * GG + 128 + j);
    float ir1 = __ldg(gi + 1 * GG + j), iz1 = __ldg(gi + 1 * GG + 64 + j), in1 = __ldg(gi + 1 * GG + 128 + j);
    __syncthreads();

    for (int t = 0; t < TT; ++t) {
        // prefetch t+2
        float fr = 0.f, fz = 0.f, fn = 0.f;
        if (t + 2 < TT) {
            const float* p = gi + (size_t)(t + 2) * GG;
            fr = __ldg(p + j); fz = __ldg(p + 64 + j); fn = __ldg(p + 128 + j);
        }

        const u64* hv = (const u64*)hbuf[t & 1][rsel];
        u64 ar0 = 0, ar1 = 0, az0 = 0, az1 = 0, an0 = 0, an1 = 0;
#pragma unroll
        for (int kk = 0; kk < 32; kk += 2) {
            const u64 h0 = hv[kk];
            const u64 h1 = hv[kk + 1];
            ar0 = fma2(wr[kk],     h0, ar0);
            ar1 = fma2(wr[kk + 1], h1, ar1);
            az0 = fma2(wz[kk],     h0, az0);
            az1 = fma2(wz[kk + 1], h1, az1);
            an0 = fma2(wn[kk],     h0, an0);
            an1 = fma2(wn[kk + 1], h1, an1);
        }
        const float hr = psum(add2(ar0, ar1)) + bhr;
        const float hz = psum(add2(az0, az1)) + bhz;
        const float hn = psum(add2(an0, an1)) + bhn;

        const float r = sigmoidf_(ir0 + hr);
        const float z = sigmoidf_(iz0 + hz);
        const float n = tanhf_(in0 + r * hn);
        const float hnew = fmaf(z, hprev - n, n);   // (1-z)*n + z*h

        hbuf[(t + 1) & 1][rsel][j] = hnew;
        hrow[(size_t)t * HID + j] = hnew;
        hprev = hnew;

        // rotate gi pipeline
        ir0 = ir1; iz0 = iz1; in0 = in1;
        ir1 = fr;  iz1 = fz;  in1 = fn;

        __syncthreads();
    }
}

// ================== K3: out proj + LN =======================================
// 256 threads / 8 warps; w2 packed in smem [k2][64] (conflict-free LDS.64);
// each warp processes 4 rows per iteration (MLP_p1=4), lane owns cols lane,lane+32.
__global__ void __launch_bounds__(256) k_outproj(const float* __restrict__ w2,
                                                 const float* __restrict__ b2,
                                                 const float* __restrict__ g2,
                                                 const float* __restrict__ bb2,
                                                 float* __restrict__ out)
{
    const int tid  = threadIdx.x;
    const int wid  = tid >> 5;
    const int lane = tid & 31;
    const int j0 = lane, j1 = lane + 32;

    __shared__ __align__(16) u64   w2p[32][64];     // 16 KB
    __shared__ __align__(16) float hst[8][4][64];   // 8 KB, per-warp staging

    for (int idx = tid; idx < 32 * 64; idx += 256) {
        const int k2 = idx >> 6, jj = idx & 63;
        w2p[k2][jj] = pack2(w2[(size_t)(2 * k2) * DPK + jj],
                            w2[(size_t)(2 * k2 + 1) * DPK + jj]);
    }
    __syncthreads();

    const float bo0 = b2[j0], bo1 = b2[j1];
    const float lg0 = g2[j0], lg1 = g2[j1];
    const float lb0 = bb2[j0], lb1 = bb2[j1];

    const size_t stride = (size_t)gridDim.x * 32;
    for (size_t base = (size_t)blockIdx.x * 32 + wid * 4; base < (size_t)NROWS;
         base += stride) {
        // 4 rows in flight (front-batched LDG.64s)
        const float2 h0 = ((const float2*)(g_hseq + (base + 0) * HID))[lane];
        const float2 h1 = ((const float2*)(g_hseq + (base + 1) * HID))[lane];
        const float2 h2 = ((const float2*)(g_hseq + (base + 2) * HID))[lane];
        const float2 h3 = ((const float2*)(g_hseq + (base + 3) * HID))[lane];
        ((float2*)hst[wid][0])[lane] = h0;
        ((float2*)hst[wid][1])[lane] = h1;
        ((float2*)hst[wid][2])[lane] = h2;
        ((float2*)hst[wid][3])[lane] = h3;
        __syncwarp();

        const u64* hA = (const u64*)hst[wid][0];
        const u64* hB = (const u64*)hst[wid][1];
        const u64* hC = (const u64*)hst[wid][2];
        const u64* hD = (const u64*)hst[wid][3];
        u64 aA0 = 0, aA1 = 0, aB0 = 0, aB1 = 0;
        u64 aC0 = 0, aC1 = 0, aD0 = 0, aD1 = 0;
#pragma unroll
        for (int k2 = 0; k2 < 32; ++k2) {
            const u64 w0 = w2p[k2][j0];
            const u64 w1 = w2p[k2][j1];
            const u64 pA = hA[k2];
            const u64 pB = hB[k2];
            const u64 pC = hC[k2];
            const u64 pD = hD[k2];
            aA0 = fma2(w0, pA, aA0);  aA1 = fma2(w1, pA, aA1);
            aB0 = fma2(w0, pB, aB0);  aB1 = fma2(w1, pB, aB1);
            aC0 = fma2(w0, pC, aC0);  aC1 = fma2(w1, pC, aC1);
            aD0 = fma2(w0, pD, aD0);  aD1 = fma2(w1, pD, aD1);
        }

        u64 acc0[4] = {aA0, aB0, aC0, aD0};
        u64 acc1[4] = {aA1, aB1, aC1, aD1};
#pragma unroll
        for (int rr = 0; rr < 4; ++rr) {
            float o0 = psum(acc0[rr]) + bo0;
            float o1 = psum(acc1[rr]) + bo1;
            float s = o0 + o1;
#pragma unroll
            for (int o = 16; o; o >>= 1) s += __shfl_xor_sync(0xffffffffu, s, o);
            const float m = s * (1.f / 64.f);
            const float d0 = o0 - m, d1 = o1 - m;
            float q = d0 * d0 + d1 * d1;
#pragma unroll
            for (int o = 16; o; o >>= 1) q += __shfl_xor_sync(0xffffffffu, q, o);
            const float rs = rsqrtf(q * (1.f / 64.f) + EPS);
            const size_t row = base + rr;
            out[row * DPK + j0] = d0 * rs * lg0 + lb0;
            out[row * DPK + j1] = d1 * rs * lg1 + lb1;
        }
        __syncwarp();   // hst slot reused next iteration
    }
}

// ================== launcher =================================================
extern "C" void kernel_launch(void* const* d_in, const int* in_sizes, int n_in,
                              void* d_out, int out_size)
{
    const float* drug = (const float*)d_in[0];
    const float* w1   = (const float*)d_in[1];
    const float* b1   = (const float*)d_in[2];
    const float* ln1g = (const float*)d_in[3];
    const float* ln1b = (const float*)d_in[4];
    const float* Wih  = (const float*)d_in[5];
    const float* bih  = (const float*)d_in[6];
    const float* Whh  = (const float*)d_in[7];
    const float* bhh  = (const float*)d_in[8];
    const float* w2   = (const float*)d_in[9];
    const float* b2   = (const float*)d_in[10];
    const float* ln2g = (const float*)d_in[11];
    const float* ln2b = (const float*)d_in[12];
    float* out = (float*)d_out;

    k_inproj<<<NROWS / 8, 256>>>(drug, w1, b1, ln1g, ln1b);
    k_gi<<<888, 192>>>(Wih, bih);
    k_gru<<<BB / 2, 128>>>(Whh, bhh);
    k_outproj<<<2048, 256>>>(w2, b2, ln2g, ln2b, out);
}

// round 4
// speedup vs baseline: 1.1945x; 1.0139x over previous
#include <cuda_runtime.h>
#include <cuda_bf16.h>
#include <cstdint>

// Problem constants
#define BB   256
#define TT   2048
#define IND  6
#define HID  64
#define GG   192          // 3*HID
#define DPK  64
#define NROWS (BB*TT)     // 524288
#define EPS  1e-5f
#define CH   2            // chains per GRU CTA

typedef unsigned long long u64;

// ---------------- scratch (allocation-free: __device__ globals) -------------
__device__ float g_x[(size_t)NROWS * HID];       // 128 MB : post input-proj activations
// gi stored TRANSPOSED, t-major: index = ((b*3 + gate)*64 + j)*TT + t
__device__ float g_gi[(size_t)NROWS * GG];       // 402 MB
__device__ float g_hseq[(size_t)NROWS * HID];    // 128 MB : GRU hidden states [b][t][j]

// ---------------- packed f32x2 helpers --------------------------------------
__device__ __forceinline__ u64 fma2(u64 a, u64 b, u64 c) {
    u64 d;
    asm("fma.rn.f32x2 %0, %1, %2, %3;" : "=l"(d) : "l"(a), "l"(b), "l"(c));
    return d;
}
__device__ __forceinline__ u64 add2(u64 a, u64 b) {
    u64 d;
    asm("add.rn.f32x2 %0, %1, %2;" : "=l"(d) : "l"(a), "l"(b));
    return d;
}
__device__ __forceinline__ u64 pack2(float a, float b) {
    u64 r;
    asm("mov.b64 %0, {%1,%2};" : "=l"(r) : "f"(a), "f"(b));
    return r;
}
__device__ __forceinline__ float psum(u64 a) {
    return __uint_as_float((unsigned)(a & 0xffffffffull)) +
           __uint_as_float((unsigned)(a >> 32));
}

__device__ __forceinline__ float sigmoidf_(float x) {
    return __fdividef(1.f, 1.f + __expf(-x));
}
__device__ __forceinline__ float tanhf_(float x) {
    float e = __expf(2.f * x);
    return 1.f - __fdividef(2.f, e + 1.f);   // safe at e->inf (->1) and e->0 (->-1)
}

// ================== K1a: input proj + LN + exact GELU ======================
// one warp per (b,t) row; each lane owns output cols lane, lane+32
__global__ void k_inproj(const float* __restrict__ ce,
                         const float* __restrict__ w1,
                         const float* __restrict__ b1,
                         const float* __restrict__ g1,
                         const float* __restrict__ bb1)
{
    const int wid  = threadIdx.x >> 5;
    const int lane = threadIdx.x & 31;
    const size_t row = (size_t)blockIdx.x * 8 + wid;   // grid = NROWS/8

    const float* c = ce + row * IND;
    float v0 = b1[lane], v1 = b1[lane + 32];
#pragma unroll
    for (int i = 0; i < IND; ++i) {
        float ci = __ldg(c + i);
        v0 = fmaf(ci, w1[i * HID + lane],      v0);
        v1 = fmaf(ci, w1[i * HID + lane + 32], v1);
    }
    float s = v0 + v1;
#pragma unroll
    for (int o = 16; o; o >>= 1) s += __shfl_xor_sync(0xffffffffu, s, o);
    const float m = s * (1.f / 64.f);
    const float d0 = v0 - m, d1 = v1 - m;
    float q = d0 * d0 + d1 * d1;
#pragma unroll
    for (int o = 16; o; o >>= 1) q += __shfl_xor_sync(0xffffffffu, q, o);
    const float rs = rsqrtf(q * (1.f / 64.f) + EPS);
    const float y0 = d0 * rs * g1[lane]      + bb1[lane];
    const float y1 = d1 * rs * g1[lane + 32] + bb1[lane + 32];
    const float k = 0.70710678118654752f;
    g_x[row * HID + lane]      = 0.5f * y0 * (1.f + erff(y0 * k));
    g_x[row * HID + lane + 32] = 0.5f * y1 * (1.f + erff(y1 * k));
}

// ================== K1b: gi = x @ W_ih^T + b_ih  (TRANSPOSED output) =======
// gate-stationary: thread g keeps W_ih[g,:] in 32 packed-u64 registers,
// 8 rows (8 consecutive t of one b) staged in smem per iteration; results
// staged in smem then written t-major: g_gi[((b*3+gate)*64+j)*TT + t0..t0+7].
__global__ void __launch_bounds__(192) k_gi(const float* __restrict__ Wih,
                                            const float* __restrict__ bih)
{
    const int g = threadIdx.x;
    u64 w[32];
    const u64* wrow = (const u64*)(Wih + g * HID);
#pragma unroll
    for (int k = 0; k < 32; ++k) w[k] = wrow[k];
    const float bi = bih[g];
    const int gate = g >> 6;
    const int j    = g & 63;

    __shared__ __align__(16) float x_sh[8 * HID];
    __shared__ float o_sh[192][9];   // pad 9 -> conflict-free (9 coprime 32)

    for (size_t r0 = (size_t)blockIdx.x * 8; r0 < (size_t)NROWS;
         r0 += (size_t)gridDim.x * 8) {
        if (g < 128)
            ((float4*)x_sh)[g] = ((const float4*)(g_x + r0 * HID))[g];
        __syncthreads();
#pragma unroll
        for (int rr = 0; rr < 8; ++rr) {
            u64 a0 = 0, a1 = 0;
            const ulonglong2* xv = (const ulonglong2*)(x_sh + rr * HID);
#pragma unroll
            for (int kk = 0; kk < 16; ++kk) {
                ulonglong2 p = xv[kk];
                a0 = fma2(w[2 * kk],     p.x, a0);
                a1 = fma2(w[2 * kk + 1], p.y, a1);
            }
            o_sh[g][rr] = psum(a0) + psum(a1) + bi;
        }
        __syncwarp();
        // transposed write: 8 consecutive t for this (b, gate, j)
        const size_t b  = r0 >> 11;           // r0 / TT
        const size_t t0 = r0 & 2047;          // r0 % TT  (multiple of 8)
        float4 lo, hi;
        lo.x = o_sh[g][0]; lo.y = o_sh[g][1]; lo.z = o_sh[g][2]; lo.w = o_sh[g][3];
        hi.x = o_sh[g][4]; hi.y = o_sh[g][5]; hi.z = o_sh[g][6]; hi.w = o_sh[g][7];
        float* dst = g_gi + (((b * 3 + gate) * 64 + j) * TT + t0);
        ((float4*)dst)[0] = lo;
        ((float4*)dst)[1] = hi;
        __syncthreads();
    }
}

// ================== K2: sequential GRU recurrence ===========================
// grid = 128 CTAs, block = 256 threads = 2 chains x 128 threads.
// Within a chain, thread pair (2j, 2j+1) K-splits the 64-wide dot for output j:
// half h in [0,2), each holds W rows' half in regs (48 u64 = 96 regs, no spill),
// partials combined with __shfl_xor(.,1) -- no smem weights, no extra barrier.
// gi is t-major: 3 x LDG.128 per 4 steps, double-buffered 2 blocks ahead.
// h double-buffered in smem; ONE __syncthreads per timestep.
__global__ void __launch_bounds__(256, 1) k_gru(const float* __restrict__ Whh,
                                                const float* __restrict__ bhh)
{
    const int tid   = threadIdx.x;
    const int chain = tid >> 7;          // 0..1
    const int c     = tid & 127;
    const int j     = c >> 1;            // 0..63
    const int half  = c & 1;             // K-half
    const size_t brow = (size_t)blockIdx.x * CH + chain;

    __shared__ float hbuf[2][CH][64];    // [phase][chain][j]

    // half of each gate's weight row, register-resident: 48 u64 = 96 regs
    u64 wr[16], wz[16], wn[16];
    {
        const u64* rrow = (const u64*)(Whh + ((size_t)j       * HID) + half * 32);
        const u64* zrow = (const u64*)(Whh + ((size_t)(64 + j) * HID) + half * 32);
        const u64* nrow = (const u64*)(Whh + ((size_t)(128 + j) * HID) + half * 32);
#pragma unroll
        for (int k = 0; k < 16; ++k) { wr[k] = rrow[k]; wz[k] = zrow[k]; wn[k] = nrow[k]; }
    }
    const float bhr = bhh[j];
    const float bhz = bhh[64 + j];
    const float bhn = bhh[128 + j];

    if (!half) hbuf[0][chain][j] = 0.f;
    float hprev = 0.f;

    const float* gr = g_gi + ((brow * 3 + 0) * 64 + j) * TT;
    const float* gz = g_gi + ((brow * 3 + 1) * 64 + j) * TT;
    const float* gn = g_gi + ((brow * 3 + 2) * 64 + j) * TT;
    float* hcol = g_hseq + brow * (size_t)TT * HID + j;

    // gi double buffer: blocks of 4 timesteps
    float4 r0b = *(const float4*)(gr + 0), z0b = *(const float4*)(gz + 0), n0b = *(const float4*)(gn + 0);
    float4 r1b = *(const float4*)(gr + 4), z1b = *(const float4*)(gz + 4), n1b = *(const float4*)(gn + 4);
    __syncthreads();

    auto step = [&](const int phase, const int t, const float ir, const float iz, const float inn) {
        const u64* hv = (const u64*)(&hbuf[phase][chain][half * 32]);
        u64 ar0 = 0, ar1 = 0, az0 = 0, az1 = 0, an0 = 0, an1 = 0;
#pragma unroll
        for (int kk = 0; kk < 16; kk += 2) {
            const u64 h0 = hv[kk];
            const u64 h1 = hv[kk + 1];
            ar0 = fma2(wr[kk],     h0, ar0);
            ar1 = fma2(wr[kk + 1], h1, ar1);
            az0 = fma2(wz[kk],     h0, az0);
            az1 = fma2(wz[kk + 1], h1, az1);
            an0 = fma2(wn[kk],     h0, an0);
            an1 = fma2(wn[kk + 1], h1, an1);
        }
        float pr = psum(add2(ar0, ar1));
        float pz = psum(add2(az0, az1));
        float pn = psum(add2(an0, an1));
        pr += __shfl_xor_sync(0xffffffffu, pr, 1);
        pz += __shfl_xor_sync(0xffffffffu, pz, 1);
        pn += __shfl_xor_sync(0xffffffffu, pn, 1);

        const float r = sigmoidf_(ir + pr + bhr);
        const float z = sigmoidf_(iz + pz + bhz);
        const float n = tanhf_(inn + r * (pn + bhn));
        const float hnew = fmaf(z, hprev - n, n);   // (1-z)*n + z*h

        if (!half) {
            hbuf[phase ^ 1][chain][j] = hnew;
            hcol[(size_t)t * HID] = hnew;
        }
        hprev = hnew;
        __syncthreads();
    };

    for (int blk = 0; blk < TT / 4; blk += 2) {
        const int t0 = blk * 4;
        // ---- block A (slot 0): prefetch blk+2 ----
        const bool pfA = (blk + 2 < TT / 4);
        float4 par, paz, pan;
        if (pfA) {
            par = *(const float4*)(gr + (blk + 2) * 4);
            paz = *(const float4*)(gz + (blk + 2) * 4);
            pan = *(const float4*)(gn + (blk + 2) * 4);
        }
        step(0, t0 + 0, r0b.x, z0b.x, n0b.x);
        step(1, t0 + 1, r0b.y, z0b.y, n0b.y);
        step(0, t0 + 2, r0b.z, z0b.z, n0b.z);
        step(1, t0 + 3, r0b.w, z0b.w, n0b.w);
        if (pfA) { r0b = par; z0b = paz; n0b = pan; }

        // ---- block B (slot 1): prefetch blk+3 ----
        const bool pfB = (blk + 3 < TT / 4);
        float4 qbr, qbz, qbn;
        if (pfB) {
            qbr = *(const float4*)(gr + (blk + 3) * 4);
            qbz = *(const float4*)(gz + (blk + 3) * 4);
            qbn = *(const float4*)(gn + (blk + 3) * 4);
        }
        step(0, t0 + 4, r1b.x, z1b.x, n1b.x);
        step(1, t0 + 5, r1b.y, z1b.y, n1b.y);
        step(0, t0 + 6, r1b.z, z1b.z, n1b.z);
        step(1, t0 + 7, r1b.w, z1b.w, n1b.w);
        if (pfB) { r1b = qbr; z1b = qbz; n1b = qbn; }
    }
}

// ================== K3: out proj + LN =======================================
// 256 threads / 8 warps; w2 packed in smem [k2][64] (conflict-free LDS.64);
// each warp processes 4 rows per iteration (MLP_p1=4), lane owns cols lane,lane+32.
__global__ void __launch_bounds__(256) k_outproj(const float* __restrict__ w2,
                                                 const float* __restrict__ b2,
                                                 const float* __restrict__ g2,
                                                 const float* __restrict__ bb2,
                                                 float* __restrict__ out)
{
    const int tid  = threadIdx.x;
    const int wid  = tid >> 5;
    const int lane = tid & 31;
    const int j0 = lane, j1 = lane + 32;

    __shared__ __align__(16) u64   w2p[32][64];     // 16 KB
    __shared__ __align__(16) float hst[8][4][64];   // 8 KB, per-warp staging

    for (int idx = tid; idx < 32 * 64; idx += 256) {
        const int k2 = idx >> 6, jj = idx & 63;
        w2p[k2][jj] = pack2(w2[(size_t)(2 * k2) * DPK + jj],
                            w2[(size_t)(2 * k2 + 1) * DPK + jj]);
    }
    __syncthreads();

    const float bo0 = b2[j0], bo1 = b2[j1];
    const float lg0 = g2[j0], lg1 = g2[j1];
    const float lb0 = bb2[j0], lb1 = bb2[j1];

    const size_t stride = (size_t)gridDim.x * 32;
    for (size_t base = (size_t)blockIdx.x * 32 + wid * 4; base < (size_t)NROWS;
         base += stride) {
        // 4 rows in flight (front-batched LDG.64s)
        const float2 h0 = ((const float2*)(g_hseq + (base + 0) * HID))[lane];
        const float2 h1 = ((const float2*)(g_hseq + (base + 1) * HID))[lane];
        const float2 h2 = ((const float2*)(g_hseq + (base + 2) * HID))[lane];
        const float2 h3 = ((const float2*)(g_hseq + (base + 3) * HID))[lane];
        ((float2*)hst[wid][0])[lane] = h0;
        ((float2*)hst[wid][1])[lane] = h1;
        ((float2*)hst[wid][2])[lane] = h2;
        ((float2*)hst[wid][3])[lane] = h3;
        __syncwarp();

        const u64* hA = (const u64*)hst[wid][0];
        const u64* hB = (const u64*)hst[wid][1];
        const u64* hC = (const u64*)hst[wid][2];
        const u64* hD = (const u64*)hst[wid][3];
        u64 aA0 = 0, aA1 = 0, aB0 = 0, aB1 = 0;
        u64 aC0 = 0, aC1 = 0, aD0 = 0, aD1 = 0;
#pragma unroll
        for (int k2 = 0; k2 < 32; ++k2) {
            const u64 w0 = w2p[k2][j0];
            const u64 w1 = w2p[k2][j1];
            const u64 pA = hA[k2];
            const u64 pB = hB[k2];
            const u64 pC = hC[k2];
            const u64 pD = hD[k2];
            aA0 = fma2(w0, pA, aA0);  aA1 = fma2(w1, pA, aA1);
            aB0 = fma2(w0, pB, aB0);  aB1 = fma2(w1, pB, aB1);
            aC0 = fma2(w0, pC, aC0);  aC1 = fma2(w1, pC, aC1);
            aD0 = fma2(w0, pD, aD0);  aD1 = fma2(w1, pD, aD1);
        }

        u64 acc0[4] = {aA0, aB0, aC0, aD0};
        u64 acc1[4] = {aA1, aB1, aC1, aD1};
#pragma unroll
        for (int rr = 0; rr < 4; ++rr) {
            float o0 = psum(acc0[rr]) + bo0;
            float o1 = psum(acc1[rr]) + bo1;
            float s = o0 + o1;
#pragma unroll
            for (int o = 16; o; o >>= 1) s += __shfl_xor_sync(0xffffffffu, s, o);
            const float m = s * (1.f / 64.f);
            const float d0 = o0 - m, d1 = o1 - m;
            float q = d0 * d0 + d1 * d1;
#pragma unroll
            for (int o = 16; o; o >>= 1) q += __shfl_xor_sync(0xffffffffu, q, o);
            const float rs = rsqrtf(q * (1.f / 64.f) + EPS);
            const size_t row = base + rr;
            out[row * DPK + j0] = d0 * rs * lg0 + lb0;
            out[row * DPK + j1] = d1 * rs * lg1 + lb1;
        }
        __syncwarp();   // hst slot reused next iteration
    }
}

// ================== launcher =================================================
extern "C" void kernel_launch(void* const* d_in, const int* in_sizes, int n_in,
                              void* d_out, int out_size)
{
    const float* drug = (const float*)d_in[0];
    const float* w1   = (const float*)d_in[1];
    const float* b1   = (const float*)d_in[2];
    const float* ln1g = (const float*)d_in[3];
    const float* ln1b = (const float*)d_in[4];
    const float* Wih  = (const float*)d_in[5];
    const float* bih  = (const float*)d_in[6];
    const float* Whh  = (const float*)d_in[7];
    const float* bhh  = (const float*)d_in[8];
    const float* w2   = (const float*)d_in[9];
    const float* b2   = (const float*)d_in[10];
    const float* ln2g = (const float*)d_in[11];
    const float* ln2b = (const float*)d_in[12];
    float* out = (float*)d_out;

    k_inproj<<<NROWS / 8, 256>>>(drug, w1, b1, ln1g, ln1b);
    k_gi<<<888, 192>>>(Wih, bih);
    k_gru<<<BB / CH, 256>>>(Whh, bhh);
    k_outproj<<<2048, 256>>>(w2, b2, ln2g, ln2b, out);
}

// round 7
// speedup vs baseline: 1.2069x; 1.0104x over previous
#include <cuda_runtime.h>
#include <cuda_bf16.h>
#include <cstdint>

// Problem constants
#define BB   256
#define TT   2048
#define IND  6
#define HID  64
#define GG   192          // 3*HID
#define DPK  64
#define NROWS (BB*TT)     // 524288
#define EPS  1e-5f
#define CH   2            // chains per GRU CTA

typedef unsigned long long u64;

// ---------------- scratch (allocation-free: __device__ globals) -------------
__device__ float g_x[(size_t)NROWS * HID];       // 128 MB : post input-proj activations
// gi stored TRANSPOSED, t-major: index = ((b*3 + gate)*64 + j)*TT + t
// biases pre-folded: r,z gates carry b_ih+b_hh; n gate carries b_ih only.
__device__ float g_gi[(size_t)NROWS * GG];       // 402 MB
__device__ float g_hseq[(size_t)NROWS * HID];    // 128 MB : GRU hidden states [b][t][j]

// ---------------- packed f32x2 helpers --------------------------------------
__device__ __forceinline__ u64 fma2(u64 a, u64 b, u64 c) {
    u64 d;
    asm("fma.rn.f32x2 %0, %1, %2, %3;" : "=l"(d) : "l"(a), "l"(b), "l"(c));
    return d;
}
__device__ __forceinline__ u64 add2(u64 a, u64 b) {
    u64 d;
    asm("add.rn.f32x2 %0, %1, %2;" : "=l"(d) : "l"(a), "l"(b));
    return d;
}
__device__ __forceinline__ u64 pack2(float a, float b) {
    u64 r;
    asm("mov.b64 %0, {%1,%2};" : "=l"(r) : "f"(a), "f"(b));
    return r;
}
__device__ __forceinline__ float psum(u64 a) {
    return __uint_as_float((unsigned)(a & 0xffffffffull)) +
           __uint_as_float((unsigned)(a >> 32));
}

// EXACT-path activations (validated rel_err ~2.5e-7 over the full recurrence
// in R1-R4). tanh.approx is not re-tried until the R5/R6 half-dot bug's
// masking of its true error contribution is quantified.
__device__ __forceinline__ float sigmoidf_(float x) {
    return __fdividef(1.f, 1.f + __expf(-x));
}
__device__ __forceinline__ float tanhf_(float x) {
    float e = __expf(2.f * x);
    return 1.f - __fdividef(2.f, e + 1.f);   // safe at e->inf (->1) and e->0 (->-1)
}

// ================== K1a: input proj + LN + exact GELU ======================
// one warp per (b,t) row; each lane owns output cols lane, lane+32
__global__ void k_inproj(const float* __restrict__ ce,
                         const float* __restrict__ w1,
                         const float* __restrict__ b1,
                         const float* __restrict__ g1,
                         const float* __restrict__ bb1)
{
    const int wid  = threadIdx.x >> 5;
    const int lane = threadIdx.x & 31;
    const size_t row = (size_t)blockIdx.x * 8 + wid;   // grid = NROWS/8

    const float* c = ce + row * IND;
    float v0 = b1[lane], v1 = b1[lane + 32];
#pragma unroll
    for (int i = 0; i < IND; ++i) {
        float ci = __ldg(c + i);
        v0 = fmaf(ci, w1[i * HID + lane],      v0);
        v1 = fmaf(ci, w1[i * HID + lane + 32], v1);
    }
    float s = v0 + v1;
#pragma unroll
    for (int o = 16; o; o >>= 1) s += __shfl_xor_sync(0xffffffffu, s, o);
    const float m = s * (1.f / 64.f);
    const float d0 = v0 - m, d1 = v1 - m;
    float q = d0 * d0 + d1 * d1;
#pragma unroll
    for (int o = 16; o; o >>= 1) q += __shfl_xor_sync(0xffffffffu, q, o);
    const float rs = rsqrtf(q * (1.f / 64.f) + EPS);
    const float y0 = d0 * rs * g1[lane]      + bb1[lane];
    const float y1 = d1 * rs * g1[lane + 32] + bb1[lane + 32];
    const float k = 0.70710678118654752f;
    g_x[row * HID + lane]      = 0.5f * y0 * (1.f + erff(y0 * k));
    g_x[row * HID + lane + 32] = 0.5f * y1 * (1.f + erff(y1 * k));
}

// ================== K1b: gi = x @ W_ih^T + bias  (TRANSPOSED output) =======
// gate-stationary: thread g keeps W_ih[g,:] in 32 packed-u64 registers,
// 8 rows (8 consecutive t of one b) staged in smem per iteration; results
// staged in smem then written t-major: g_gi[((b*3+gate)*64+j)*TT + t0..t0+7].
// Bias folding: gates r,z get b_ih+b_hh; gate n gets b_ih only.
__global__ void __launch_bounds__(192) k_gi(const float* __restrict__ Wih,
                                            const float* __restrict__ bih,
                                            const float* __restrict__ bhh)
{
    const int g = threadIdx.x;
    u64 w[32];
    const u64* wrow = (const u64*)(Wih + g * HID);
#pragma unroll
    for (int k = 0; k < 32; ++k) w[k] = wrow[k];
    const int gate = g >> 6;
    const int j    = g & 63;
    const float bi = bih[g] + (gate < 2 ? bhh[g] : 0.f);

    __shared__ __align__(16) float x_sh[8 * HID];
    __shared__ float o_sh[192][9];   // pad 9 -> conflict-free (9 coprime 32)

    for (size_t r0 = (size_t)blockIdx.x * 8; r0 < (size_t)NROWS;
         r0 += (size_t)gridDim.x * 8) {
        if (g < 128)
            ((float4*)x_sh)[g] = ((const float4*)(g_x + r0 * HID))[g];
        __syncthreads();
#pragma unroll
        for (int rr = 0; rr < 8; ++rr) {
            u64 a0 = 0, a1 = 0;
            const ulonglong2* xv = (const ulonglong2*)(x_sh + rr * HID);
#pragma unroll
            for (int kk = 0; kk < 16; ++kk) {
                ulonglong2 p = xv[kk];
                a0 = fma2(w[2 * kk],     p.x, a0);
                a1 = fma2(w[2 * kk + 1], p.y, a1);
            }
            o_sh[g][rr] = psum(a0) + psum(a1) + bi;
        }
        __syncwarp();
        // transposed write: 8 consecutive t for this (b, gate, j)
        const size_t b  = r0 >> 11;           // r0 / TT
        const size_t t0 = r0 & 2047;          // r0 % TT  (multiple of 8)
        float4 lo, hi;
        lo.x = o_sh[g][0]; lo.y = o_sh[g][1]; lo.z = o_sh[g][2]; lo.w = o_sh[g][3];
        hi.x = o_sh[g][4]; hi.y = o_sh[g][5]; hi.z = o_sh[g][6]; hi.w = o_sh[g][7];
        float* dst = g_gi + (((b * 3 + gate) * 64 + j) * TT + t0);
        ((float4*)dst)[0] = lo;
        ((float4*)dst)[1] = hi;
        __syncthreads();
    }
}

// ================== K2: sequential GRU recurrence ===========================
// grid = 128 CTAs, block = 128 threads = 2 chains x 64 threads (2 warps each).
// Thread (chain, j) owns output j: ALL THREE gate rows register-resident
// (96 u64 = 192 regs), FULL 64-wide dots (16 x LDS.128 broadcast -- the
// R5/R6 bug was stopping at 8, i.e. half-width dots). 1 warp per SMSP.
// h double-buffered in smem. Per-chain named barrier (bar.sync id,64).
// EXACT activations. gi t-major; each scalar reloaded in place right after
// consumption (prefetch distance = 4 steps ~ 1600cyc) -> only 12 buffer regs.
__global__ void __launch_bounds__(128, 1) k_gru(const float* __restrict__ Whh,
                                                const float* __restrict__ bhh)
{
    const int tid   = threadIdx.x;
    const int chain = tid >> 6;          // 0..1
    const int j     = tid & 63;
    const size_t brow = (size_t)blockIdx.x * CH + chain;
    const unsigned barid = 1 + chain;

    __shared__ __align__(16) float hbuf[2][CH][64];  // [phase][chain][j]

    // all three gate rows register-resident: 96 u64
    u64 wr[32], wz[32], wn[32];
    {
        const u64* rrow = (const u64*)(Whh + (size_t)j * HID);
        const u64* zrow = (const u64*)(Whh + (size_t)(64 + j) * HID);
        const u64* nrow = (const u64*)(Whh + (size_t)(128 + j) * HID);
#pragma unroll
        for (int k = 0; k < 32; ++k) { wr[k] = rrow[k]; wz[k] = zrow[k]; wn[k] = nrow[k]; }
    }
    const float bhn = bhh[128 + j];   // only n-gate hidden bias kept (inside r*(..))

    hbuf[0][chain][j] = 0.f;
    float hprev = 0.f;

    const float* gr = g_gi + ((brow * 3 + 0) * 64 + j) * TT;
    const float* gz = g_gi + ((brow * 3 + 1) * 64 + j) * TT;
    const float* gn = g_gi + ((brow * 3 + 2) * 64 + j) * TT;
    float* hcol = g_hseq + brow * (size_t)TT * HID + j;

    // gi block buffer (one 4-step block = 12 scalars); each scalar reloaded
    // in place immediately after use with the value 4 steps ahead.
    float cr0 = __ldg(gr + 0), cr1 = __ldg(gr + 1), cr2 = __ldg(gr + 2), cr3 = __ldg(gr + 3);
    float cz0 = __ldg(gz + 0), cz1 = __ldg(gz + 1), cz2 = __ldg(gz + 2), cz3 = __ldg(gz + 3);
    float cn0 = __ldg(gn + 0), cn1 = __ldg(gn + 1), cn2 = __ldg(gn + 2), cn3 = __ldg(gn + 3);

    asm volatile("bar.sync %0, 64;" :: "r"(barid) : "memory");

    auto step = [&](const int phase, const int t, const float ir, const float iz, const float inn) {
        const ulonglong2* hv = (const ulonglong2*)hbuf[phase][chain];
        u64 ar0 = 0, ar1 = 0, az0 = 0, az1 = 0, an0 = 0, an1 = 0;
#pragma unroll
        for (int kk = 0; kk < 16; ++kk) {      // FULL 64-wide dot: 16 x LDS.128
            const ulonglong2 p = hv[kk];
            ar0 = fma2(wr[2 * kk],     p.x, ar0);
            ar1 = fma2(wr[2 * kk + 1], p.y, ar1);
            az0 = fma2(wz[2 * kk],     p.x, az0);
            az1 = fma2(wz[2 * kk + 1], p.y, az1);
            an0 = fma2(wn[2 * kk],     p.x, an0);
            an1 = fma2(wn[2 * kk + 1], p.y, an1);
        }
        const float pr = psum(add2(ar0, ar1));
        const float pz = psum(add2(az0, az1));
        const float pn = psum(add2(an0, an1));

        const float r = sigmoidf_(ir + pr);             // biases pre-folded in gi
        const float z = sigmoidf_(iz + pz);
        const float n = tanhf_(inn + r * (pn + bhn));
        const float hnew = fmaf(z, hprev - n, n);       // (1-z)*n + z*h

        hbuf[phase ^ 1][chain][j] = hnew;
        hcol[(size_t)t * HID] = hnew;
        hprev = hnew;
        asm volatile("bar.sync %0, 64;" :: "r"(barid) : "memory");
    };

#pragma unroll 1
    for (int blk = 0; blk < TT / 4; ++blk) {
        const int t0 = blk * 4;
        const bool pf = (blk + 1 < TT / 4);
        const float* pr4 = gr + (blk + 1) * 4;
        const float* pz4 = gz + (blk + 1) * 4;
        const float* pn4 = gn + (blk + 1) * 4;

        { const float ir = cr0, iz = cz0, inn = cn0;
          if (pf) { cr0 = __ldg(pr4 + 0); cz0 = __ldg(pz4 + 0); cn0 = __ldg(pn4 + 0); }
          step(0, t0 + 0, ir, iz, inn); }
        { const float ir = cr1, iz = cz1, inn = cn1;
          if (pf) { cr1 = __ldg(pr4 + 1); cz1 = __ldg(pz4 + 1); cn1 = __ldg(pn4 + 1); }
          step(1, t0 + 1, ir, iz, inn); }
        { const float ir = cr2, iz = cz2, inn = cn2;
          if (pf) { cr2 = __ldg(pr4 + 2); cz2 = __ldg(pz4 + 2); cn2 = __ldg(pn4 + 2); }
          step(0, t0 + 2, ir, iz, inn); }
        { const float ir = cr3, iz = cz3, inn = cn3;
          if (pf) { cr3 = __ldg(pr4 + 3); cz3 = __ldg(pz4 + 3); cn3 = __ldg(pn4 + 3); }
          step(1, t0 + 3, ir, iz, inn); }
    }
}

// ================== K3: out proj + LN =======================================
// 256 threads / 8 warps; w2 packed in smem [k2][64] (conflict-free LDS.64);
// each warp processes 4 rows per iteration (MLP_p1=4), lane owns cols lane,lane+32.
__global__ void __launch_bounds__(256) k_outproj(const float* __restrict__ w2,
                                                 const float* __restrict__ b2,
                                                 const float* __restrict__ g2,
                                                 const float* __restrict__ bb2,
                                                 float* __restrict__ out)
{
    const int tid  = threadIdx.x;
    const int wid  = tid >> 5;
    const int lane = tid & 31;
    const int j0 = lane, j1 = lane + 32;

    __shared__ __align__(16) u64   w2p[32][64];     // 16 KB
    __shared__ __align__(16) float hst[8][4][64];   // 8 KB, per-warp staging

    for (int idx = tid; idx < 32 * 64; idx += 256) {
        const int k2 = idx >> 6, jj = idx & 63;
        w2p[k2][jj] = pack2(w2[(size_t)(2 * k2) * DPK + jj],
                            w2[(size_t)(2 * k2 + 1) * DPK + jj]);
    }
    __syncthreads();

    const float bo0 = b2[j0], bo1 = b2[j1];
    const float lg0 = g2[j0], lg1 = g2[j1];
    const float lb0 = bb2[j0], lb1 = bb2[j1];

    const size_t stride = (size_t)gridDim.x * 32;
    for (size_t base = (size_t)blockIdx.x * 32 + wid * 4; base < (size_t)NROWS;
         base += stride) {
        // 4 rows in flight (front-batched LDG.64s)
        const float2 h0 = ((const float2*)(g_hseq + (base + 0) * HID))[lane];
        const float2 h1 = ((const float2*)(g_hseq + (base + 1) * HID))[lane];
        const float2 h2 = ((const float2*)(g_hseq + (base + 2) * HID))[lane];
        const float2 h3 = ((const float2*)(g_hseq + (base + 3) * HID))[lane];
        ((float2*)hst[wid][0])[lane] = h0;
        ((float2*)hst[wid][1])[lane] = h1;
        ((float2*)hst[wid][2])[lane] = h2;
        ((float2*)hst[wid][3])[lane] = h3;
        __syncwarp();

        const u64* hA = (const u64*)hst[wid][0];
        const u64* hB = (const u64*)hst[wid][1];
        const u64* hC = (const u64*)hst[wid][2];
        const u64* hD = (const u64*)hst[wid][3];
        u64 aA0 = 0, aA1 = 0, aB0 = 0, aB1 = 0;
        u64 aC0 = 0, aC1 = 0, aD0 = 0, aD1 = 0;
#pragma unroll
        for (int k2 = 0; k2 < 32; ++k2) {
            const u64 w0 = w2p[k2][j0];
            const u64 w1 = w2p[k2][j1];
            const u64 pA = hA[k2];
            const u64 pB = hB[k2];
            const u64 pC = hC[k2];
            const u64 pD = hD[k2];
            aA0 = fma2(w0, pA, aA0);  aA1 = fma2(w1, pA, aA1);
            aB0 = fma2(w0, pB, aB0);  aB1 = fma2(w1, pB, aB1);
            aC0 = fma2(w0, pC, aC0);  aC1 = fma2(w1, pC, aC1);
            aD0 = fma2(w0, pD, aD0);  aD1 = fma2(w1, pD, aD1);
        }

        u64 acc0[4] = {aA0, aB0, aC0, aD0};
        u64 acc1[4] = {aA1, aB1, aC1, aD1};
#pragma unroll
        for (int rr = 0; rr < 4; ++rr) {
            float o0 = psum(acc0[rr]) + bo0;
            float o1 = psum(acc1[rr]) + bo1;
            float s = o0 + o1;
#pragma unroll
            for (int o = 16; o; o >>= 1) s += __shfl_xor_sync(0xffffffffu, s, o);
            const float m = s * (1.f / 64.f);
            const float d0 = o0 - m, d1 = o1 - m;
            float q = d0 * d0 + d1 * d1;
#pragma unroll
            for (int o = 16; o; o >>= 1) q += __shfl_xor_sync(0xffffffffu, q, o);
            const float rs = rsqrtf(q * (1.f / 64.f) + EPS);
            const size_t row = base + rr;
            out[row * DPK + j0] = d0 * rs * lg0 + lb0;
            out[row * DPK + j1] = d1 * rs * lg1 + lb1;
        }
        __syncwarp();   // hst slot reused next iteration
    }
}

// ================== launcher =================================================
extern "C" void kernel_launch(void* const* d_in, const int* in_sizes, int n_in,
                              void* d_out, int out_size)
{
    const float* drug = (const float*)d_in[0];
    const float* w1   = (const float*)d_in[1];
    const float* b1   = (const float*)d_in[2];
    const float* ln1g = (const float*)d_in[3];
    const float* ln1b = (const float*)d_in[4];
    const float* Wih  = (const float*)d_in[5];
    const float* bih  = (const float*)d_in[6];
    const float* Whh  = (const float*)d_in[7];
    const float* bhh  = (const float*)d_in[8];
    const float* w2   = (const float*)d_in[9];
    const float* b2   = (const float*)d_in[10];
    const float* ln2g = (const float*)d_in[11];
    const float* ln2b = (const float*)d_in[12];
    float* out = (float*)d_out;

    k_inproj<<<NROWS / 8, 256>>>(drug, w1, b1, ln1g, ln1b);
    k_gi<<<888, 192>>>(Wih, bih, bhh);
    k_gru<<<BB / CH, 128>>>(Whh, bhh);
    k_outproj<<<2048, 256>>>(w2, b2, ln2g, ln2b, out);
}

// round 8
// speedup vs baseline: 1.3741x; 1.1385x over previous
#include <cuda_runtime.h>
#include <cuda_bf16.h>
#include <cstdint>

// Problem constants
#define BB   256
#define TT   2048
#define IND  6
#define HID  64
#define GG   192          // 3*HID
#define DPK  64
#define NROWS (BB*TT)     // 524288
#define EPS  1e-5f
#define CH   2            // chains per GRU CTA

typedef unsigned long long u64;

// ---------------- scratch (allocation-free: __device__ globals) -------------
__device__ float g_x[(size_t)NROWS * HID];       // 128 MB : post input-proj activations
// gi J-MAJOR: index = row*GG + gate*64 + j  (warp-coalesced loads in k_gru!)
// biases pre-folded: r,z gates carry b_ih+b_hh; n gate carries b_ih only.
__device__ float g_gi[(size_t)NROWS * GG];       // 402 MB
__device__ float g_hseq[(size_t)NROWS * HID];    // 128 MB : GRU hidden states [b][t][j]

// ---------------- packed f32x2 helpers --------------------------------------
__device__ __forceinline__ u64 fma2(u64 a, u64 b, u64 c) {
    u64 d;
    asm("fma.rn.f32x2 %0, %1, %2, %3;" : "=l"(d) : "l"(a), "l"(b), "l"(c));
    return d;
}
__device__ __forceinline__ u64 pack2(float a, float b) {
    u64 r;
    asm("mov.b64 %0, {%1,%2};" : "=l"(r) : "f"(a), "f"(b));
    return r;
}
__device__ __forceinline__ float psum(u64 a) {
    return __uint_as_float((unsigned)(a & 0xffffffffull)) +
           __uint_as_float((unsigned)(a >> 32));
}

// EXACT-path activations (validated rel_err ~2.5e-7 over the full recurrence).
__device__ __forceinline__ float sigmoidf_(float x) {
    return __fdividef(1.f, 1.f + __expf(-x));
}
__device__ __forceinline__ float tanhf_(float x) {
    float e = __expf(2.f * x);
    return 1.f - __fdividef(2.f, e + 1.f);   // safe at e->inf (->1) and e->0 (->-1)
}

// ================== K1a: input proj + LN + exact GELU ======================
// one warp per (b,t) row; each lane owns output cols lane, lane+32
__global__ void k_inproj(const float* __restrict__ ce,
                         const float* __restrict__ w1,
                         const float* __restrict__ b1,
                         const float* __restrict__ g1,
                         const float* __restrict__ bb1)
{
    const int wid  = threadIdx.x >> 5;
    const int lane = threadIdx.x & 31;
    const size_t row = (size_t)blockIdx.x * 8 + wid;   // grid = NROWS/8

    const float* c = ce + row * IND;
    float v0 = b1[lane], v1 = b1[lane + 32];
#pragma unroll
    for (int i = 0; i < IND; ++i) {
        float ci = __ldg(c + i);
        v0 = fmaf(ci, w1[i * HID + lane],      v0);
        v1 = fmaf(ci, w1[i * HID + lane + 32], v1);
    }
    float s = v0 + v1;
#pragma unroll
    for (int o = 16; o; o >>= 1) s += __shfl_xor_sync(0xffffffffu, s, o);
    const float m = s * (1.f / 64.f);
    const float d0 = v0 - m, d1 = v1 - m;
    float q = d0 * d0 + d1 * d1;
#pragma unroll
    for (int o = 16; o; o >>= 1) q += __shfl_xor_sync(0xffffffffu, q, o);
    const float rs = rsqrtf(q * (1.f / 64.f) + EPS);
    const float y0 = d0 * rs * g1[lane]      + bb1[lane];
    const float y1 = d1 * rs * g1[lane + 32] + bb1[lane + 32];
    const float k = 0.70710678118654752f;
    g_x[row * HID + lane]      = 0.5f * y0 * (1.f + erff(y0 * k));
    g_x[row * HID + lane + 32] = 0.5f * y1 * (1.f + erff(y1 * k));
}

// ================== K1b: gi = x @ W_ih^T + bias  (j-major output) ==========
// gate-stationary: thread g keeps W_ih[g,:] in 32 packed-u64 registers,
// 8 rows of x staged in smem per iteration; direct coalesced output write.
// Bias folding: gates r,z get b_ih+b_hh; gate n gets b_ih only.
__global__ void __launch_bounds__(192) k_gi(const float* __restrict__ Wih,
                                            const float* __restrict__ bih,
                                            const float* __restrict__ bhh)
{
    const int g = threadIdx.x;
    u64 w[32];
    const u64* wrow = (const u64*)(Wih + g * HID);
#pragma unroll
    for (int k = 0; k < 32; ++k) w[k] = wrow[k];
    const int gate = g >> 6;
    const float bi = bih[g] + (gate < 2 ? bhh[g] : 0.f);

    __shared__ __align__(16) float x_sh[8 * HID];

    for (size_t r0 = (size_t)blockIdx.x * 8; r0 < (size_t)NROWS;
         r0 += (size_t)gridDim.x * 8) {
        if (g < 128)
            ((float4*)x_sh)[g] = ((const float4*)(g_x + r0 * HID))[g];
        __syncthreads();
#pragma unroll
        for (int rr = 0; rr < 8; ++rr) {
            u64 a0 = 0, a1 = 0;
            const ulonglong2* xv = (const ulonglong2*)(x_sh + rr * HID);
#pragma unroll
            for (int kk = 0; kk < 16; ++kk) {
                ulonglong2 p = xv[kk];
                a0 = fma2(w[2 * kk],     p.x, a0);
                a1 = fma2(w[2 * kk + 1], p.y, a1);
            }
            g_gi[(r0 + rr) * GG + g] = psum(a0) + psum(a1) + bi;
        }
        __syncthreads();
    }
}

// ================== K2: sequential GRU recurrence ===========================
// grid = 128 CTAs, block = 128 threads = 2 chains x 64 threads (2 warps each).
// Thread (chain, j) owns output j: ALL THREE gate rows register-resident
// (96 u64), full 64-wide dots, 1 warp/SMSP, per-chain named barrier.
// h history lives in a 16-slot smem RING (doubles as the h exchange buffer);
// every 8 steps it is flushed to g_hseq with coalesced STG.128 (8 wavefronts
// per 8 steps vs 256 for the old per-step scattered STG.32).
// gi is j-major -> the 3 per-step LDG.32 are warp-coalesced (1 line each).
__global__ void __launch_bounds__(128, 1) k_gru(const float* __restrict__ Whh,
                                                const float* __restrict__ bhh)
{
    const int tid   = threadIdx.x;
    const int chain = tid >> 6;          // 0..1
    const int j     = tid & 63;
    const size_t brow = (size_t)blockIdx.x * CH + chain;
    const unsigned barid = 1 + chain;

    __shared__ __align__(16) float ring[16][CH][64];  // 8 KB h history

    // all three gate rows register-resident: 96 u64
    u64 wr[32], wz[32], wn[32];
    {
        const u64* rrow = (const u64*)(Whh + (size_t)j * HID);
        const u64* zrow = (const u64*)(Whh + (size_t)(64 + j) * HID);
        const u64* nrow = (const u64*)(Whh + (size_t)(128 + j) * HID);
#pragma unroll
        for (int k = 0; k < 32; ++k) { wr[k] = rrow[k]; wz[k] = zrow[k]; wn[k] = nrow[k]; }
    }
    const float bhn = bhh[128 + j];   // only n-gate hidden bias kept (inside r*(..))

    ring[15][chain][j] = 0.f;        // h_{-1} = 0
    float hprev = 0.f;

    const float* gib = g_gi + brow * (size_t)TT * GG + j;   // + t*GG + gate*64
    float* hbase = g_hseq + brow * (size_t)TT * HID;

    // gi block buffer: current 4 steps (12 scalars), each reloaded in place
    // right after consumption with the value 4 steps ahead (coalesced LDG.32).
    float cr0 = __ldg(gib + 0 * GG),       cz0 = __ldg(gib + 0 * GG + 64),  cn0 = __ldg(gib + 0 * GG + 128);
    float cr1 = __ldg(gib + 1 * GG),       cz1 = __ldg(gib + 1 * GG + 64),  cn1 = __ldg(gib + 1 * GG + 128);
    float cr2 = __ldg(gib + 2 * GG),       cz2 = __ldg(gib + 2 * GG + 64),  cn2 = __ldg(gib + 2 * GG + 128);
    float cr3 = __ldg(gib + 3 * GG),       cz3 = __ldg(gib + 3 * GG + 64),  cn3 = __ldg(gib + 3 * GG + 128);

    asm volatile("bar.sync %0, 64;" :: "r"(barid) : "memory");

    auto step = [&](const int t, const float ir, const float iz, const float inn) {
        const ulonglong2* hv = (const ulonglong2*)ring[(t + 15) & 15][chain];
        u64 ar = 0, az = 0, an = 0;            // single accum chain per gate
#pragma unroll
        for (int kk = 0; kk < 16; ++kk) {      // full 64-wide dot: 16 x LDS.128
            const ulonglong2 p = hv[kk];
            ar = fma2(wr[2 * kk],     p.x, ar);
            az = fma2(wz[2 * kk],     p.x, az);
            an = fma2(wn[2 * kk],     p.x, an);
            ar = fma2(wr[2 * kk + 1], p.y, ar);
            az = fma2(wz[2 * kk + 1], p.y, az);
            an = fma2(wn[2 * kk + 1], p.y, an);
        }
        const float pr = psum(ar);
        const float pz = psum(az);
        const float pn = psum(an);

        const float r = sigmoidf_(ir + pr);             // biases pre-folded in gi
        const float z = sigmoidf_(iz + pz);
        const float n = tanhf_(inn + r * (pn + bhn));
        const float hnew = fmaf(z, hprev - n, n);       // (1-z)*n + z*h

        ring[t & 15][chain][j] = hnew;
        hprev = hnew;
        asm volatile("bar.sync %0, 64;" :: "r"(barid) : "memory");
    };

#pragma unroll 1
    for (int blk = 0; blk < TT / 4; ++blk) {
        const int t0 = blk * 4;
        const bool pf = (blk + 1 < TT / 4);
        const float* p = gib + (size_t)(t0 + 4) * GG;

        { const float ir = cr0, iz = cz0, inn = cn0;
          if (pf) { cr0 = __ldg(p + 0 * GG); cz0 = __ldg(p + 0 * GG + 64); cn0 = __ldg(p + 0 * GG + 128); }
          step(t0 + 0, ir, iz, inn); }
        { const float ir = cr1, iz = cz1, inn = cn1;
          if (pf) { cr1 = __ldg(p + 1 * GG); cz1 = __ldg(p + 1 * GG + 64); cn1 = __ldg(p + 1 * GG + 128); }
          step(t0 + 1, ir, iz, inn); }
        { const float ir = cr2, iz = cz2, inn = cn2;
          if (pf) { cr2 = __ldg(p + 2 * GG); cz2 = __ldg(p + 2 * GG + 64); cn2 = __ldg(p + 2 * GG + 128); }
          step(t0 + 2, ir, iz, inn); }
        { const float ir = cr3, iz = cz3, inn = cn3;
          if (pf) { cr3 = __ldg(p + 3 * GG); cz3 = __ldg(p + 3 * GG + 64); cn3 = __ldg(p + 3 * GG + 128); }
          step(t0 + 3, ir, iz, inn); }

        if (blk & 1) {
            // flush steps tb..tb+7 (ring slots (tb&15)..+7), coalesced.
            // Safe: these slots are next overwritten >= 9 barriers later.
            const int tb = t0 - 4;               // multiple of 8
            const int sb = tb & 15;              // 0 or 8
#pragma unroll
            for (int q = 0; q < 2; ++q) {
                const int idx  = q * 64 + j;     // 0..127
                const int toff = idx >> 4;       // 0..7
                const int jq   = idx & 15;       // float4 index within row
                const float4 v = ((const float4*)ring[sb + toff][chain])[jq];
                ((float4*)(hbase + (size_t)(tb + toff) * HID))[jq] = v;
            }
        }
    }
}

// ================== K3: out proj + LN =======================================
// 256 threads / 8 warps; w2 packed in smem [k2][64] (conflict-free LDS.64);
// each warp processes 4 rows per iteration (MLP_p1=4), lane owns cols lane,lane+32.
__global__ void __launch_bounds__(256) k_outproj(const float* __restrict__ w2,
                                                 const float* __restrict__ b2,
                                                 const float* __restrict__ g2,
                                                 const float* __restrict__ bb2,
                                                 float* __restrict__ out)
{
    const int tid  = threadIdx.x;
    const int wid  = tid >> 5;
    const int lane = tid & 31;
    const int j0 = lane, j1 = lane + 32;

    __shared__ __align__(16) u64   w2p[32][64];     // 16 KB
    __shared__ __align__(16) float hst[8][4][64];   // 8 KB, per-warp staging

    for (int idx = tid; idx < 32 * 64; idx += 256) {
        const int k2 = idx >> 6, jj = idx & 63;
        w2p[k2][jj] = pack2(w2[(size_t)(2 * k2) * DPK + jj],
                            w2[(size_t)(2 * k2 + 1) * DPK + jj]);
    }
    __syncthreads();

    const float bo0 = b2[j0], bo1 = b2[j1];
    const float lg0 = g2[j0], lg1 = g2[j1];
    const float lb0 = bb2[j0], lb1 = bb2[j1];

    const size_t stride = (size_t)gridDim.x * 32;
    for (size_t base = (size_t)blockIdx.x * 32 + wid * 4; base < (size_t)NROWS;
         base += stride) {
        // 4 rows in flight (front-batched LDG.64s)
        const float2 h0 = ((const float2*)(g_hseq + (base + 0) * HID))[lane];
        const float2 h1 = ((const float2*)(g_hseq + (base + 1) * HID))[lane];
        const float2 h2 = ((const float2*)(g_hseq + (base + 2) * HID))[lane];
        const float2 h3 = ((const float2*)(g_hseq + (base + 3) * HID))[lane];
        ((float2*)hst[wid][0])[lane] = h0;
        ((float2*)hst[wid][1])[lane] = h1;
        ((float2*)hst[wid][2])[lane] = h2;
        ((float2*)hst[wid][3])[lane] = h3;
        __syncwarp();

        const u64* hA = (const u64*)hst[wid][0];
        const u64* hB = (const u64*)hst[wid][1];
        const u64* hC = (const u64*)hst[wid][2];
        const u64* hD = (const u64*)hst[wid][3];
        u64 aA0 = 0, aA1 = 0, aB0 = 0, aB1 = 0;
        u64 aC0 = 0, aC1 = 0, aD0 = 0, aD1 = 0;
#pragma unroll
        for (int k2 = 0; k2 < 32; ++k2) {
            const u64 w0 = w2p[k2][j0];
            const u64 w1 = w2p[k2][j1];
            const u64 pA = hA[k2];
            const u64 pB = hB[k2];
            const u64 pC = hC[k2];
            const u64 pD = hD[k2];
            aA0 = fma2(w0, pA, aA0);  aA1 = fma2(w1, pA, aA1);
            aB0 = fma2(w0, pB, aB0);  aB1 = fma2(w1, pB, aB1);
            aC0 = fma2(w0, pC, aC0);  aC1 = fma2(w1, pC, aC1);
            aD0 = fma2(w0, pD, aD0);  aD1 = fma2(w1, pD, aD1);
        }

        u64 acc0[4] = {aA0, aB0, aC0, aD0};
        u64 acc1[4] = {aA1, aB1, aC1, aD1};
#pragma unroll
        for (int rr = 0; rr < 4; ++rr) {
            float o0 = psum(acc0[rr]) + bo0;
            float o1 = psum(acc1[rr]) + bo1;
            float s = o0 + o1;
#pragma unroll
            for (int o = 16; o; o >>= 1) s += __shfl_xor_sync(0xffffffffu, s, o);
            const float m = s * (1.f / 64.f);
            const float d0 = o0 - m, d1 = o1 - m;
            float q = d0 * d0 + d1 * d1;
#pragma unroll
            for (int o = 16; o; o >>= 1) q += __shfl_xor_sync(0xffffffffu, q, o);
            const float rs = rsqrtf(q * (1.f / 64.f) + EPS);
            const size_t row = base + rr;
            out[row * DPK + j0] = d0 * rs * lg0 + lb0;
            out[row * DPK + j1] = d1 * rs * lg1 + lb1;
        }
        __syncwarp();   // hst slot reused next iteration
    }
}

// ================== launcher =================================================
extern "C" void kernel_launch(void* const* d_in, const int* in_sizes, int n_in,
                              void* d_out, int out_size)
{
    const float* drug = (const float*)d_in[0];
    const float* w1   = (const float*)d_in[1];
    const float* b1   = (const float*)d_in[2];
    const float* ln1g = (const float*)d_in[3];
    const float* ln1b = (const float*)d_in[4];
    const float* Wih  = (const float*)d_in[5];
    const float* bih  = (const float*)d_in[6];
    const float* Whh  = (const float*)d_in[7];
    const float* bhh  = (const float*)d_in[8];
    const float* w2   = (const float*)d_in[9];
    const float* b2   = (const float*)d_in[10];
    const float* ln2g = (const float*)d_in[11];
    const float* ln2b = (const float*)d_in[12];
    float* out = (float*)d_out;

    k_inproj<<<NROWS / 8, 256>>>(drug, w1, b1, ln1g, ln1b);
    k_gi<<<888, 192>>>(Wih, bih, bhh);
    k_gru<<<BB / CH, 128>>>(Whh, bhh);
    k_outproj<<<2048, 256>>>(w2, b2, ln2g, ln2b, out);
}